// round 1
// baseline (speedup 1.0000x reference)
#include <cuda_runtime.h>
#include <cub/cub.cuh>

#define NTOT   270072
#define NTOP   6000
#define NKEEP  1000
#define NWORDS 94          // ceil(6000/64)
#define KTOT   2304        // 256*9

// ------------------------- static device scratch -------------------------
__device__ float  g_wT[KTOT * 256];                       // transposed conv weights [k][co]
__device__ float  g_t[(size_t)2 * 256 * 192 * 352];       // conv output, biggest level (reused)
__device__ float  g_scores[2 * NTOT];
__device__ float4 g_boxes4[2 * NTOT];
__device__ int    g_iota[NTOT];
__device__ float  g_skeys[2 * NTOT];
__device__ int    g_sidx[2 * NTOT];
__device__ float4 g_topb4[2 * NTOP];
__device__ float  g_tops[2 * NTOP];
__device__ unsigned long long g_mask[(size_t)2 * NTOP * NWORDS];
__device__ int    g_keep[2 * NKEEP];
__device__ int    g_nkeep[2];
__device__ unsigned char g_cubtmp[32u * 1024u * 1024u];

// ------------------------- weight transpose ------------------------------
__global__ void k_transposeW(const float* __restrict__ w) {
    int i = blockIdx.x * 256 + threadIdx.x;
    if (i < 256 * KTOT) {
        int co = i / KTOT;
        int k  = i - co * KTOT;
        g_wT[(size_t)k * 256 + co] = w[i];
    }
}

__global__ void k_iota() {
    int i = blockIdx.x * 256 + threadIdx.x;
    if (i < NTOT) g_iota[i] = i;
}

// ------------------------- conv3x3 256->256 + bias + relu ----------------
// Implicit GEMM: C[64 pixels][64 co], K = 2304, tiles of 16.
__global__ __launch_bounds__(256) void k_conv3x3(const float* __restrict__ x,
                                                 const float* __restrict__ bias,
                                                 int H, int W) {
    __shared__ float As[16][64];
    __shared__ float Bs[16][64];
    __shared__ int   sB[64], sY[64], sX[64];

    const int tid  = threadIdx.x;
    const int HW   = H * W;
    const int Npix = 2 * HW;
    const int pBase  = blockIdx.x * 64;
    const int coBase = blockIdx.y * 64;

    if (tid < 64) {
        int pg = pBase + tid;
        int b = -1, y = 0, xw = 0;
        if (pg < Npix) {
            b = (pg >= HW) ? 1 : 0;
            int hw = pg - b * HW;
            y  = hw / W;
            xw = hw - y * W;
        }
        sB[tid] = b; sY[tid] = y; sX[tid] = xw;
    }
    __syncthreads();

    float acc[4][4];
#pragma unroll
    for (int i = 0; i < 4; i++)
#pragma unroll
        for (int j = 0; j < 4; j++) acc[i][j] = 0.f;

    const int tx = tid & 15, ty = tid >> 4;

    for (int kt = 0; kt < KTOT; kt += 16) {
        // load A tile (64 pixels x 16 k)
#pragma unroll
        for (int r = 0; r < 4; r++) {
            int idx = tid + r * 256;
            int kk  = idx >> 6;
            int p   = idx & 63;
            int k   = kt + kk;
            int ci  = k / 9;
            int rem = k - ci * 9;
            int kh  = rem / 3;
            int kw  = rem - kh * 3;
            float v = 0.f;
            int b = sB[p];
            if (b >= 0) {
                int iy = sY[p] + kh - 1;
                int ix = sX[p] + kw - 1;
                if ((unsigned)iy < (unsigned)H && (unsigned)ix < (unsigned)W)
                    v = __ldg(&x[(((size_t)(b * 256 + ci)) * H + iy) * W + ix]);
            }
            As[kk][p] = v;
        }
        // load B tile (16 k x 64 co) -- coalesced from transposed weights
#pragma unroll
        for (int r = 0; r < 4; r++) {
            int idx = tid + r * 256;
            int kk  = idx >> 6;
            int c   = idx & 63;
            Bs[kk][c] = g_wT[(size_t)(kt + kk) * 256 + coBase + c];
        }
        __syncthreads();

#pragma unroll
        for (int kk = 0; kk < 16; kk++) {
            float a0 = As[kk][ty * 4 + 0];
            float a1 = As[kk][ty * 4 + 1];
            float a2 = As[kk][ty * 4 + 2];
            float a3 = As[kk][ty * 4 + 3];
            float b0 = Bs[kk][tx * 4 + 0];
            float b1 = Bs[kk][tx * 4 + 1];
            float b2 = Bs[kk][tx * 4 + 2];
            float b3 = Bs[kk][tx * 4 + 3];
            acc[0][0] = fmaf(a0, b0, acc[0][0]); acc[0][1] = fmaf(a0, b1, acc[0][1]);
            acc[0][2] = fmaf(a0, b2, acc[0][2]); acc[0][3] = fmaf(a0, b3, acc[0][3]);
            acc[1][0] = fmaf(a1, b0, acc[1][0]); acc[1][1] = fmaf(a1, b1, acc[1][1]);
            acc[1][2] = fmaf(a1, b2, acc[1][2]); acc[1][3] = fmaf(a1, b3, acc[1][3]);
            acc[2][0] = fmaf(a2, b0, acc[2][0]); acc[2][1] = fmaf(a2, b1, acc[2][1]);
            acc[2][2] = fmaf(a2, b2, acc[2][2]); acc[2][3] = fmaf(a2, b3, acc[2][3]);
            acc[3][0] = fmaf(a3, b0, acc[3][0]); acc[3][1] = fmaf(a3, b1, acc[3][1]);
            acc[3][2] = fmaf(a3, b2, acc[3][2]); acc[3][3] = fmaf(a3, b3, acc[3][3]);
        }
        __syncthreads();
    }

#pragma unroll
    for (int i = 0; i < 4; i++) {
        int p = ty * 4 + i;
        int b = sB[p];
        if (b < 0) continue;
        size_t base = (((size_t)b * 256) * H + sY[p]) * W + sX[p];
#pragma unroll
        for (int j = 0; j < 4; j++) {
            int co = coBase + tx * 4 + j;
            float v = acc[i][j] + __ldg(&bias[co]);
            g_t[base + (size_t)co * HW] = fmaxf(v, 0.f);
        }
    }
}

// ------------------------- heads: 1x1 convs + softmax + decode -----------
__global__ __launch_bounds__(256) void k_heads(const float* __restrict__ cls_w,
                                               const float* __restrict__ cls_b,
                                               const float* __restrict__ bbox_w,
                                               const float* __restrict__ bbox_b,
                                               const float* __restrict__ im_info,
                                               int H, int W, int offs, int levelOff) {
    __shared__ float st[256][33];
    __shared__ float so[18][32];

    const int tid  = threadIdx.x;
    const int HW   = H * W;
    const int Npix = 2 * HW;
    const int P0   = blockIdx.x * 32;

    {
        int cr = tid >> 5;
        int p  = tid & 31;
        int pg = P0 + p;
        bool pv = pg < Npix;
        size_t base = 0;
        if (pv) {
            int b  = (pg >= HW) ? 1 : 0;
            int hw = pg - b * HW;
            int y  = hw / W;
            int xw = hw - y * W;
            base = (((size_t)b * 256) * H + y) * W + xw;
        }
        for (int c0 = 0; c0 < 256; c0 += 8) {
            int c = c0 + cr;
            st[c][p] = pv ? g_t[base + (size_t)c * HW] : 0.f;
        }
    }
    __syncthreads();

    if (tid < 192) {
        int pp = tid & 31;
        int og = tid >> 5;          // 0..5 -> output rows og*3 .. og*3+2
        int o0 = og * 3;
        const float* wr = (o0 < 6) ? (cls_w + o0 * 256) : (bbox_w + (o0 - 6) * 256);
        float a0 = 0.f, a1 = 0.f, a2 = 0.f;
#pragma unroll 8
        for (int c = 0; c < 256; c++) {
            float v = st[c][pp];
            a0 = fmaf(v, __ldg(wr + c),        a0);
            a1 = fmaf(v, __ldg(wr + 256 + c),  a1);
            a2 = fmaf(v, __ldg(wr + 512 + c),  a2);
        }
        if (o0 < 6) { a0 += cls_b[o0]; a1 += cls_b[o0 + 1]; a2 += cls_b[o0 + 2]; }
        else { a0 += bbox_b[o0 - 6]; a1 += bbox_b[o0 - 5]; a2 += bbox_b[o0 - 4]; }
        so[o0][pp] = a0; so[o0 + 1][pp] = a1; so[o0 + 2][pp] = a2;
    }
    __syncthreads();

    if (tid < 96) {
        int pp = tid / 3;
        int a  = tid - pp * 3;
        int pg = P0 + pp;
        if (pg < Npix) {
            int bb = (pg >= HW) ? 1 : 0;
            int hw = pg - bb * HW;
            int yy = hw / W;
            int xx = hw - yy * W;

            float l0 = so[2 * a][pp], l1 = so[2 * a + 1][pp];
            float m  = fmaxf(l0, l1);
            float e0 = expf(l0 - m), e1 = expf(l1 - m);
            float score = e1 / (e0 + e1);

            float d0 = so[6 + 4 * a + 0][pp];
            float d1 = so[6 + 4 * a + 1][pp];
            float d2 = so[6 + 4 * a + 2][pp];
            float d3 = so[6 + 4 * a + 3][pp];

            const float wsA[3] = {16.f, 11.f, 9.f};
            const float hsA[3] = {16.f, 22.f, 27.f};
            float scale  = 2.f * (float)offs;
            float stride = 4.f * (float)offs;
            float aw = wsA[a] * scale, ah = hsA[a] * scale;
            float sx = (float)xx * stride, sy = (float)yy * stride;
            float ax = 8.f + sx;           // exact: ctr(7.5)+0.5 + shift
            float ay = 8.f + sy;

            float px = ax + d0 * aw;
            float py = ay + d1 * ah;
            float pw = aw * expf(d2);
            float ph = ah * expf(d3);
            float x1 = px - 0.5f * pw, x2 = px + 0.5f * pw;
            float y1 = py - 0.5f * ph, y2 = py + 0.5f * ph;

            float imh = im_info[bb * 6 + 0];
            float imw = im_info[bb * 6 + 1];
            float isc = im_info[bb * 6 + 2];
            x1 = fminf(fmaxf(x1, 0.f), imw - 1.f);
            y1 = fminf(fmaxf(y1, 0.f), imh - 1.f);
            x2 = fminf(fmaxf(x2, 0.f), imw - 1.f);
            y2 = fminf(fmaxf(y2, 0.f), imh - 1.f);

            float thr = 2.f * isc;
            if (!((x2 - x1 + 1.f) >= thr && (y2 - y1 + 1.f) >= thr)) score = -1.f;

            int gi = levelOff + (yy * W + xx) * 3 + a;
            g_scores[bb * NTOT + gi] = score;
            float4 bx; bx.x = x1; bx.y = y1; bx.z = x2; bx.w = y2;
            g_boxes4[bb * NTOT + gi] = bx;
        }
    }
}

// ------------------------- top-k gather ----------------------------------
__global__ void k_gather() {
    int r = blockIdx.x * 256 + threadIdx.x;
    if (r < 2 * NTOP) {
        int b = r / NTOP;
        int k = r - b * NTOP;
        int idx = g_sidx[b * NTOT + k];
        g_tops[r]  = g_skeys[b * NTOT + k];
        g_topb4[r] = g_boxes4[b * NTOT + idx];
    }
}

// ------------------------- NMS suppression mask --------------------------
__global__ __launch_bounds__(64) void k_mask() {
    int b = blockIdx.z;
    int row = blockIdx.y * 64 + threadIdx.x;
    int colBase = blockIdx.x * 64;

    __shared__ float4 cb[64];
    int j0 = colBase + threadIdx.x;
    cb[threadIdx.x] = (j0 < NTOP) ? g_topb4[b * NTOP + j0] : make_float4(0, 0, 0, 0);
    __syncthreads();
    if (row >= NTOP) return;

    float4 rb = g_topb4[b * NTOP + row];
    float rarea = (rb.z - rb.x + 1.f) * (rb.w - rb.y + 1.f);
    unsigned long long bits = 0ull;
    int nmax = min(64, NTOP - colBase);
    for (int t = 0; t < nmax; t++) {
        int j = colBase + t;
        if (j == row) continue;
        float4 ob = cb[t];
        float ix1 = fmaxf(rb.x, ob.x), iy1 = fmaxf(rb.y, ob.y);
        float ix2 = fminf(rb.z, ob.z), iy2 = fminf(rb.w, ob.w);
        float iw = fmaxf(ix2 - ix1 + 1.f, 0.f);
        float ih = fmaxf(iy2 - iy1 + 1.f, 0.f);
        float inter = iw * ih;
        float oarea = (ob.z - ob.x + 1.f) * (ob.w - ob.y + 1.f);
        float iou = inter / (rarea + oarea - inter);
        if (iou > 0.7f) bits |= (1ull << t);
    }
    g_mask[((size_t)b * NTOP + row) * NWORDS + blockIdx.x] = bits;
}

// ------------------------- greedy NMS scan (1 warp / image) --------------
__global__ void k_scan() {
    int b = blockIdx.x;
    int lane = threadIdx.x;
    unsigned long long remv0 = 0ull, remv1 = 0ull, remv2 = 0ull;
    int kept = 0;
    for (int i = 0; i < NTOP && kept < NKEEP; i++) {
        int w = i >> 6;
        int bit = i & 63;
        int owner = w & 31;
        int slot = w >> 5;
        unsigned long long wd = (slot == 0) ? remv0 : (slot == 1) ? remv1 : remv2;
        wd = __shfl_sync(0xffffffffu, wd, owner);
        bool sup = (wd >> bit) & 1ull;
        if (!sup && g_tops[b * NTOP + i] > -0.5f) {
            if (lane == 0) g_keep[b * NKEEP + kept] = i;
            kept++;
            const unsigned long long* mrow = &g_mask[((size_t)b * NTOP + i) * NWORDS];
            int w0 = lane;
            int w1 = lane + 32;
            int w2 = lane + 64;
            remv0 |= mrow[w0];
            remv1 |= mrow[w1];
            if (w2 < NWORDS) remv2 |= mrow[w2];
        }
    }
    if (lane == 0) g_nkeep[b] = kept;
}

// ------------------------- output ROIs -----------------------------------
__global__ void k_output(float* __restrict__ out) {
    int r = blockIdx.x * 256 + threadIdx.x;
    if (r < 2 * NKEEP) {
        int b = r / NKEEP;
        int k = r - b * NKEEP;
        float v0 = 0.f, v1 = 0.f, v2 = 0.f, v3 = 0.f, v4 = 0.f;
        if (k < g_nkeep[b]) {
            int i = g_keep[b * NKEEP + k];
            float4 bx = g_topb4[b * NTOP + i];
            v0 = (float)b; v1 = bx.x; v2 = bx.y; v3 = bx.z; v4 = bx.w;
        }
        out[r * 5 + 0] = v0;
        out[r * 5 + 1] = v1;
        out[r * 5 + 2] = v2;
        out[r * 5 + 3] = v3;
        out[r * 5 + 4] = v4;
    }
}

// ------------------------- host launcher ---------------------------------
extern "C" void kernel_launch(void* const* d_in, const int* in_sizes, int n_in,
                              void* d_out, int out_size) {
    (void)in_sizes; (void)n_in; (void)out_size;
    const float* f[5];
    for (int i = 0; i < 5; i++) f[i] = (const float*)d_in[i];
    const float* rpn_w   = (const float*)d_in[5];
    const float* rpn_b   = (const float*)d_in[6];
    const float* cls_w   = (const float*)d_in[7];
    const float* cls_b   = (const float*)d_in[8];
    const float* bbox_w  = (const float*)d_in[9];
    const float* bbox_b  = (const float*)d_in[10];
    const float* im_info = (const float*)d_in[11];

    static const int Hs[5]   = {12, 24, 48, 96, 192};
    static const int Ws[5]   = {22, 44, 88, 176, 352};
    static const int OFF[5]  = {16, 8, 4, 2, 1};
    static const int LOFF[5] = {0, 792, 3960, 16632, 67320};

    k_transposeW<<<(256 * KTOT + 255) / 256, 256>>>(rpn_w);
    k_iota<<<(NTOT + 255) / 256, 256>>>();

    for (int l = 0; l < 5; l++) {
        int H = Hs[l], W = Ws[l];
        int Npix = 2 * H * W;
        dim3 g((Npix + 63) / 64, 4);
        k_conv3x3<<<g, 256>>>(f[l], rpn_b, H, W);
        k_heads<<<(Npix + 31) / 32, 256>>>(cls_w, cls_b, bbox_w, bbox_b, im_info,
                                           H, W, OFF[l], LOFF[l]);
    }

    // device pointers for CUB
    float *scores, *skeys;
    int *iota, *sidx;
    void* tmp;
    cudaGetSymbolAddress((void**)&scores, g_scores);
    cudaGetSymbolAddress((void**)&skeys,  g_skeys);
    cudaGetSymbolAddress((void**)&iota,   g_iota);
    cudaGetSymbolAddress((void**)&sidx,   g_sidx);
    cudaGetSymbolAddress(&tmp,            g_cubtmp);

    for (int b = 0; b < 2; b++) {
        size_t need = 0;
        cub::DeviceRadixSort::SortPairsDescending(nullptr, need,
            scores + b * NTOT, skeys + b * NTOT, iota, sidx + b * NTOT, NTOT);
        if (need <= sizeof(g_cubtmp)) {
            cub::DeviceRadixSort::SortPairsDescending(tmp, need,
                scores + b * NTOT, skeys + b * NTOT, iota, sidx + b * NTOT, NTOT);
        }
    }

    k_gather<<<(2 * NTOP + 255) / 256, 256>>>();
    dim3 gm(NWORDS, NWORDS, 2);
    k_mask<<<gm, 64>>>();
    k_scan<<<2, 32>>>();
    k_output<<<(2 * NKEEP + 255) / 256, 256>>>((float*)d_out);
}